// round 16
// baseline (speedup 1.0000x reference)
#include <cuda_runtime.h>
#include <cuda_fp16.h>
#include <math.h>
#include <cstdint>

#define B_  8
#define T_  1024
#define C_  1024
#define H_  16
#define D_  64
#define M_  (B_*T_)    // 8192
#define HD_ (H_*D_)    // 1024
#define NQKV_ (3*HD_)  // 3072

// ---------------- scratch (static device globals) ----------------
__device__ unsigned short g_xhi[M_*C_];                      // x fp16 [M][K]
__device__ unsigned short g_bhi[NQKV_*C_];                   // qkv W fp16 as B[n][k]
__device__ unsigned short g_phi[C_*HD_];                     // proj W fp16 as B[n][k]
__device__ unsigned short g_atthi[M_*HD_];                   // attn out fp16 [M][HD]
__device__ unsigned short g_qhi[B_*H_*T_*D_], g_qlo[B_*H_*T_*D_];  // [b,h,t,d]
__device__ unsigned short g_khi[B_*H_*T_*D_], g_klo[B_*H_*T_*D_];  // [b,h,t,d]
__device__ unsigned short g_vhi[B_*H_*T_*D_];                // TRANSPOSED: [b,h,d,t]

// ---------------- helpers ----------------
__device__ __forceinline__ uint32_t smem_u32(const void* p) {
    uint32_t a;
    asm("{ .reg .u64 t; cvta.to.shared.u64 t, %1; cvt.u32.u64 %0, t; }" : "=r"(a) : "l"(p));
    return a;
}
__device__ __forceinline__ void cp16(uint32_t dst, const void* src) {
    asm volatile("cp.async.cg.shared.global [%0], [%1], 16;" :: "r"(dst), "l"(src));
}
#define CP_COMMIT() asm volatile("cp.async.commit_group;" ::: "memory")
#define CP_WAIT0()  asm volatile("cp.async.wait_group 0;" ::: "memory")

__device__ __forceinline__ void ldsm_x4(uint32_t* r, uint32_t addr) {
    asm volatile("ldmatrix.sync.aligned.m8n8.x4.shared.b16 {%0,%1,%2,%3}, [%4];"
        : "=r"(r[0]), "=r"(r[1]), "=r"(r[2]), "=r"(r[3]) : "r"(addr));
}
__device__ __forceinline__ void mma16816(float* d, const uint32_t* a, const uint32_t* b) {
    asm volatile("mma.sync.aligned.m16n8k16.row.col.f32.f16.f16.f32 "
        "{%0,%1,%2,%3}, {%4,%5,%6,%7}, {%8,%9}, {%0,%1,%2,%3};"
        : "+f"(d[0]), "+f"(d[1]), "+f"(d[2]), "+f"(d[3])
        : "r"(a[0]), "r"(a[1]), "r"(a[2]), "r"(a[3]), "r"(b[0]), "r"(b[1]));
}
__device__ __forceinline__ void split_h(float v, __half& hi, __half& lo) {
    hi = __float2half_rn(v);
    lo = __float2half_rn(v - __half2float(hi));
}
__device__ __forceinline__ uint32_t packh2(float a, float b) {
    __half2 t = __floats2half2_rn(a, b);
    return *(uint32_t*)&t;
}
// fast exp2 on FMA pipe, degree-5 (x <= 0 expected; clamped)
__device__ __forceinline__ float exp2fast(float x) {
    x = fmaxf(x, -120.0f);
    float t = x + 12582912.0f;
    int   n = __float_as_int(t) - 0x4B400000;
    float f = x - (t - 12582912.0f);
    float p = fmaf(f, 0.0015403f, 0.0096181f);
    p = fmaf(f, p, 0.0555041f);
    p = fmaf(f, p, 0.2402265f);
    p = fmaf(f, p, 0.6931472f);
    p = fmaf(f, p, 1.0f);
    return __int_as_float(__float_as_int(p) + (n << 23));
}

// ---------------------------------------------------------------------------
// Single merged conversion kernel: everything -> fp16 hi only.
// ---------------------------------------------------------------------------
#define NXB   (M_*C_/4/256)         // 8192
#define NWPB  1024
#define CONV_BLOCKS (NXB + NWPB + 3*512)

__global__ __launch_bounds__(256) void conv_all_kernel(
    const float* __restrict__ x,  const float* __restrict__ Wp,
    const float* __restrict__ Wq, const float* __restrict__ Wk,
    const float* __restrict__ Wv)
{
    const int bi = blockIdx.x;
    if (bi < NXB) {
        int i = bi * 256 + threadIdx.x;
        float4 v = ((const float4*)x)[i];
        __half2* ph = (__half2*)g_xhi;
        ph[i*2]   = __floats2half2_rn(v.x, v.y);
        ph[i*2+1] = __floats2half2_rn(v.z, v.w);
    } else if (bi < NXB + NWPB) {
        __shared__ float tile[32][33];
        const int idx = bi - NXB;
        const int bx = idx >> 5, by = idx & 31;
        const int tx = threadIdx.x & 31, ty = threadIdx.x >> 5;
#pragma unroll
        for (int r = 0; r < 4; r++)
            tile[ty + 8*r][tx] = Wp[(size_t)(by*32 + ty + 8*r) * C_ + bx*32 + tx];
        __syncthreads();
#pragma unroll
        for (int r = 0; r < 4; r++) {
            float v = tile[tx][ty + 8*r];
            size_t id = (size_t)(bx*32 + ty + 8*r) * C_ + by*32 + tx;
            ((__half*)g_phi)[id] = __float2half_rn(v);
        }
    } else {
        __shared__ float tile[32][65];
        const int idx = bi - NXB - NWPB;          // 0..1535
        const int sel = idx >> 9;                 // 0=q,1=k,2=v
        const int id2 = idx & 511;
        const int h = id2 & 15, kt = id2 >> 4;
        const int n0 = sel << 10;
        const float* W = (sel == 0) ? Wq : ((sel == 1) ? Wk : Wv);
        const int tid = threadIdx.x;
        const float* src = W + (size_t)h * (C_ * D_) + (size_t)kt * 32 * D_;
#pragma unroll
        for (int i = 0; i < 8; i++) {
            int u = i * 256 + tid;
            tile[u >> 6][u & 63] = src[(size_t)(u >> 6) * D_ + (u & 63)];
        }
        __syncthreads();
        const int d = tid >> 2, seg = tid & 3;
        __half2* dh = (__half2*)(g_bhi + (size_t)(n0 + h*64 + d) * C_ + kt*32 + seg*8);
#pragma unroll
        for (int j = 0; j < 4; j++)
            dh[j] = __floats2half2_rn(tile[seg*8 + j*2][d], tile[seg*8 + j*2 + 1][d]);
    }
}

// ---------------------------------------------------------------------------
// Pure fp16 1-pass GEMM. CTA tile 128 x 256, 8 warps, warp tile 64x64.
// MODE 0: x * qkvW -> Q/K [t][d] split hi/lo + V^T [d][t] fp16.
// MODE 1: att * projW -> out + bias.
// ---------------------------------------------------------------------------
#define ROWB        144
#define A_BYTES     (128*ROWB)      // 18432
#define B_BYTES     (256*ROWB)      // 36864
#define OFF_AHI     0
#define OFF_BHI     A_BYTES
#define STAGE_BYTES (A_BYTES + B_BYTES)       // 55296
#define GEMM_SMEM   (2*STAGE_BYTES)           // 110592
#define NCHUNK      16

template<int MODE>
__global__ __launch_bounds__(256, 1) void gemm_kernel(const float* __restrict__ bias,
                                                      float* __restrict__ out) {
    extern __shared__ char smem[];
    const int tid  = threadIdx.x;
    const int wid  = tid >> 5;
    const int lane = tid & 31;
    const int m0 = blockIdx.x * 128;
    const int n0 = blockIdx.y * 256;

    const __half* Ahi = (MODE == 0) ? (const __half*)g_xhi : (const __half*)g_atthi;
    const __half* Bhi = (MODE == 0) ? (const __half*)g_bhi : (const __half*)g_phi;

    const uint32_t sb0 = smem_u32(smem);

    auto load_stage = [&](int c, int s) {
        const uint32_t base = sb0 + s * STAGE_BYTES;
        const int k0 = c * 64;
#pragma unroll
        for (int i = 0; i < 4; i++) {
            int u = i * 256 + tid;
            int r = u >> 3, kc = (u & 7) * 8;
            uint32_t doff = r * ROWB + (u & 7) * 16;
            cp16(base + OFF_AHI + doff, Ahi + (size_t)(m0 + r) * C_ + k0 + kc);
        }
#pragma unroll
        for (int i = 0; i < 8; i++) {
            int u = i * 256 + tid;
            int r = u >> 3, kc = (u & 7) * 8;
            uint32_t doff = r * ROWB + (u & 7) * 16;
            cp16(base + OFF_BHI + doff, Bhi + (size_t)(n0 + r) * C_ + k0 + kc);
        }
    };

    const int warp_m = wid & 1;      // 2 x 64 rows
    const int warp_n = wid >> 1;     // 4 x 64 cols
    const int mati = lane >> 3;
    const int ri   = lane & 7;

    float acc[4][8][4];
#pragma unroll
    for (int a = 0; a < 4; a++)
#pragma unroll
        for (int b = 0; b < 8; b++)
#pragma unroll
            for (int c = 0; c < 4; c++) acc[a][b][c] = 0.0f;

    load_stage(0, 0); CP_COMMIT();

    for (int c = 0; c < NCHUNK; c++) {
        CP_WAIT0();
        __syncthreads();
        if (c + 1 < NCHUNK) { load_stage(c + 1, (c + 1) & 1); CP_COMMIT(); }

        const uint32_t base = sb0 + (c & 1) * STAGE_BYTES;
#pragma unroll
        for (int kc = 0; kc < 64; kc += 16) {
            uint32_t ah[4][4];
#pragma unroll
            for (int mt = 0; mt < 4; mt++) {
                int row = warp_m*64 + mt*16 + ri + (mati & 1) * 8;
                int kk  = kc + (mati >> 1) * 8;
                ldsm_x4(ah[mt], base + OFF_AHI + row * ROWB + kk * 2);
            }
            uint32_t bh[4][4];
#pragma unroll
            for (int nt4 = 0; nt4 < 4; nt4++) {
                int n  = warp_n*64 + nt4*16 + ri + (mati >> 1) * 8;
                int kk = kc + (mati & 1) * 8;
                ldsm_x4(bh[nt4], base + OFF_BHI + n * ROWB + kk * 2);
            }
#pragma unroll
            for (int mt = 0; mt < 4; mt++)
#pragma unroll
                for (int nt = 0; nt < 8; nt++)
                    mma16816(acc[mt][nt], ah[mt], &bh[nt >> 1][(nt & 1) * 2]);
        }
        __syncthreads();
    }

    const int r4 = lane >> 2;
    const int c2 = (lane & 3) * 2;
#pragma unroll
    for (int mt = 0; mt < 4; mt++) {
#pragma unroll
        for (int nt = 0; nt < 8; nt++) {
            const int n = n0 + warp_n*64 + nt*8 + c2;
#pragma unroll
            for (int half = 0; half < 2; half++) {
                const int row = m0 + warp_m*64 + mt*16 + r4 + half*8;
                float2 v = make_float2(acc[mt][nt][half*2], acc[mt][nt][half*2 + 1]);
                if (MODE == 0) {
                    const int type = n >> 10;
                    const int bb = row >> 10, tt = row & 1023;
                    const int h2 = (n & 1023) >> 6, d2 = n & 63;
                    if (type == 2) {
                        // V transposed fp16: [b,h,d,t]
                        const size_t idx = ((size_t)(bb*H_ + h2) * D_ + d2) * T_ + tt;
                        ((__half*)g_vhi)[idx]      = __float2half_rn(v.x);
                        ((__half*)g_vhi)[idx + T_] = __float2half_rn(v.y);
                    } else {
                        unsigned short* dh = (type == 0) ? g_qhi : g_khi;
                        unsigned short* dl = (type == 0) ? g_qlo : g_klo;
                        const size_t idx = (size_t)(((bb*H_ + h2)*T_ + tt)) * D_ + d2;
                        __half hx, lx, hy, ly;
                        split_h(v.x, hx, lx); split_h(v.y, hy, ly);
                        *(__half2*)(dh + idx) = __halves2half2(hx, hy);
                        *(__half2*)(dl + idx) = __halves2half2(lx, ly);
                    }
                } else {
                    float2 bv = *(const float2*)(bias + n);
                    v.x += bv.x; v.y += bv.y;
                    *(float2*)(out + (size_t)row * C_ + n) = v;
                }
            }
        }
    }
}

// ---------------------------------------------------------------------------
// Tensor-core causal flash attention (round-15 validated, unchanged).
// QK 3-pass (corrects Q/K storage rounding), PV 1-pass. One sync per tile.
// ---------------------------------------------------------------------------
#define AROWB     144
#define VROWB     272
#define A_QHI     0
#define A_QLO     18432
#define A_STAGE0  36864
#define A_STAGEB  54272
#define A_KHI     0
#define A_KLO     18432
#define A_VHI     36864
#define ATTN_SMEM 145408
#define SCL       0.18033688f   // 0.125 * log2(e)

__global__ __launch_bounds__(256, 1) void attn_kernel() {
    extern __shared__ char smem[];
    const uint32_t sb = smem_u32(smem);
    const int tid = threadIdx.x, wid = tid >> 5, lane = tid & 31;
    const int qb = 7 - (int)blockIdx.x;                 // heavy blocks first
    const int h = blockIdx.y, b = blockIdx.z;
    const size_t hoff = (size_t)(b*H_ + h) * T_ * D_;

    const __half* Qh = (const __half*)g_qhi + hoff;
    const __half* Ql = (const __half*)g_qlo + hoff;
    const __half* Kh = (const __half*)g_khi + hoff;
    const __half* Kl = (const __half*)g_klo + hoff;
    const __half* Vh = (const __half*)g_vhi + hoff;    // [d][t]

    const int nkt = qb + 1;
    const int ri = lane & 7, mati = lane >> 3;

    auto load_kv = [&](int kt, int st) {
        const uint32_t base = sb + A_STAGE0 + st * A_STAGEB;
#pragma unroll
        for (int i = 0; i < 4; i++) {
            int u = i * 256 + tid;                  // 0..1023
            int r = u >> 3, cc = u & 7;
            const size_t off = (size_t)(kt*128 + r) * D_ + cc*8;
            uint32_t doff = r * AROWB + cc * 16;
            cp16(base + A_KHI + doff, Kh + off);
            cp16(base + A_KLO + doff, Kl + off);
        }
#pragma unroll
        for (int i = 0; i < 4; i++) {
            int u = i * 256 + tid;                  // 0..1023
            int r = u >> 4, cc = u & 15;
            const size_t off = (size_t)r * T_ + kt*128 + cc*8;
            uint32_t doff = r * VROWB + cc * 16;
            cp16(base + A_VHI + doff, Vh + off);
        }
    };

    // Q tile (128 x 64)
#pragma unroll
    for (int i = 0; i < 4; i++) {
        int u = i * 256 + tid;
        int r = u >> 3, cc = u & 7;
        const size_t off = (size_t)(qb*128 + r) * D_ + cc*8;
        uint32_t doff = r * AROWB + cc * 16;
        cp16(sb + A_QHI + doff, Qh + off);
        cp16(sb + A_QLO + doff, Ql + off);
    }
    load_kv(0, 0);
    CP_COMMIT();

    float o[8][4];
#pragma unroll
    for (int j = 0; j < 8; j++)
#pragma unroll
        for (int e = 0; e < 4; e++) o[j][e] = 0.0f;
    float mA = -1e30f, mB = -1e30f, lA = 0.0f, lB = 0.0f;
    uint32_t qhf[4][4], qlf[4][4];

    const int w0 = qb*128 + wid*16;
    const int rA = w0 + (lane >> 2);
    const int rB = rA + 8;

    for (int kt = 0; kt < nkt; kt++) {
        CP_WAIT0();
        __syncthreads();
        if (kt + 1 < nkt) { load_kv(kt + 1, (kt + 1) & 1); CP_COMMIT(); }

        const uint32_t kvb = sb + A_STAGE0 + (kt & 1) * A_STAGEB;

        if (kt == 0) {
#pragma unroll
            for (int t = 0; t < 4; t++) {
                int row = wid*16 + ri + (mati & 1) * 8;
                int kk  = t*16 + (mati >> 1) * 8;
                ldsm_x4(qhf[t], sb + A_QHI + row * AROWB + kk * 2);
                ldsm_x4(qlf[t], sb + A_QLO + row * AROWB + kk * 2);
            }
        }

        // ---- S = Q K^T over 128 keys (3-pass, pass-major) ----
        float s[16][4];
#pragma unroll
        for (int j = 0; j < 16; j++)
#pragma unroll
            for (int e = 0; e < 4; e++) s[j][e] = 0.0f;
#pragma unroll
        for (int half = 0; half < 2; half++) {
#pragma unroll
            for (int t = 0; t < 4; t++) {
                uint32_t kh[4][4], kl[4][4];
#pragma unroll
                for (int g = 0; g < 4; g++) {
                    int n  = half*64 + g*16 + ri + (mati >> 1) * 8;
                    int kk = t*16 + (mati & 1) * 8;
                    ldsm_x4(kh[g], kvb + A_KHI + n * AROWB + kk * 2);
                    ldsm_x4(kl[g], kvb + A_KLO + n * AROWB + kk * 2);
                }
#pragma unroll
                for (int nt = 0; nt < 8; nt++)
                    mma16816(s[half*8 + nt], qhf[t], &kh[nt >> 1][(nt & 1) * 2]);
#pragma unroll
                for (int nt = 0; nt < 8; nt++)
                    mma16816(s[half*8 + nt], qhf[t], &kl[nt >> 1][(nt & 1) * 2]);
#pragma unroll
                for (int nt = 0; nt < 8; nt++)
                    mma16816(s[half*8 + nt], qlf[t], &kh[nt >> 1][(nt & 1) * 2]);
            }
        }

        // ---- scale (log2 domain) + causal mask (only final tile masks) ----
        const bool need_mask = (kt == qb);
#pragma unroll
        for (int sg = 0; sg < 16; sg++) {
#pragma unroll
            for (int e = 0; e < 4; e++) {
                float v = s[sg][e] * SCL;
                if (need_mask) {
                    const int col = kt*128 + sg*8 + (lane & 3)*2 + (e & 1);
                    const int row = (e < 2) ? rA : rB;
                    if (col > row) v = -1e30f;
                }
                s[sg][e] = v;
            }
        }

        // ---- online softmax ----
        float mxA = -1e30f, mxB = -1e30f;
#pragma unroll
        for (int sg = 0; sg < 16; sg++) {
            mxA = fmaxf(mxA, fmaxf(s[sg][0], s[sg][1]));
            mxB = fmaxf(mxB, fmaxf(s[sg][2], s[sg][3]));
        }
#pragma unroll
        for (int off = 1; off <= 2; off <<= 1) {
            mxA = fmaxf(mxA, __shfl_xor_sync(0xffffffffu, mxA, off));
            mxB = fmaxf(mxB, __shfl_xor_sync(0xffffffffu, mxB, off));
        }
        const float mAn = fmaxf(mA, mxA), mBn = fmaxf(mB, mxB);
        const float fA = exp2fast(mA - mAn), fB = exp2fast(mB - mBn);
        float sumA = 0.0f, sumB = 0.0f;
#pragma unroll
        for (int sg = 0; sg < 16; sg++) {
            s[sg][0] = exp2fast(s[sg][0] - mAn);
            s[sg][1] = exp2fast(s[sg][1] - mAn);
            s[sg][2] = exp2fast(s[sg][2] - mBn);
            s[sg][3] = exp2fast(s[sg][3] - mBn);
            sumA += s[sg][0] + s[sg][1];
            sumB += s[sg][2] + s[sg][3];
        }
#pragma unroll
        for (int off = 1; off <= 2; off <<= 1) {
            sumA += __shfl_xor_sync(0xffffffffu, sumA, off);
            sumB += __shfl_xor_sync(0xffffffffu, sumB, off);
        }
        lA = lA * fA + sumA;
        lB = lB * fB + sumB;
        mA = mAn; mB = mBn;
#pragma unroll
        for (int nt = 0; nt < 8; nt++) {
            o[nt][0] *= fA; o[nt][1] *= fA;
            o[nt][2] *= fB; o[nt][3] *= fB;
        }

        // ---- P -> fp16 A fragments (registers only) ----
        uint32_t pa[8][4];
#pragma unroll
        for (int t = 0; t < 8; t++) {
            pa[t][0] = packh2(s[2*t][0],   s[2*t][1]);
            pa[t][1] = packh2(s[2*t][2],   s[2*t][3]);
            pa[t][2] = packh2(s[2*t+1][0], s[2*t+1][1]);
            pa[t][3] = packh2(s[2*t+1][2], s[2*t+1][3]);
        }

        // ---- O += P V (1-pass), V^T tile + plain ldmatrix ----
#pragma unroll
        for (int t = 0; t < 8; t++) {
            uint32_t vh[4][4];
#pragma unroll
            for (int g = 0; g < 4; g++) {
                int n  = g*16 + ri + (mati >> 1) * 8;       // d row of V^T
                int kk = t*16 + (mati & 1) * 8;             // key col
                ldsm_x4(vh[g], kvb + A_VHI + n * VROWB + kk * 2);
            }
#pragma unroll
            for (int nt = 0; nt < 8; nt++)
                mma16816(o[nt], pa[t], &vh[nt >> 1][(nt & 1) * 2]);
        }
        // no trailing sync: next iteration's top sync orders stage reuse
    }

    // ---- epilogue: normalize + fp16 att ----
    const float iA = 1.0f / lA, iB = 1.0f / lB;
#pragma unroll
    for (int nt = 0; nt < 8; nt++) {
        const int col = h*64 + nt*8 + (lane & 3)*2;
        {
            const size_t idx = (size_t)(b*T_ + rA) * HD_ + col;
            *(__half2*)((__half*)g_atthi + idx) =
                __floats2half2_rn(o[nt][0] * iA, o[nt][1] * iA);
        }
        {
            const size_t idx = (size_t)(b*T_ + rB) * HD_ + col;
            *(__half2*)((__half*)g_atthi + idx) =
                __floats2half2_rn(o[nt][2] * iB, o[nt][3] * iB);
        }
    }
}

// ---------------------------------------------------------------------------
extern "C" void kernel_launch(void* const* d_in, const int* in_sizes, int n_in,
                              void* d_out, int out_size)
{
    (void)in_sizes; (void)n_in; (void)out_size;
    const float* x    = (const float*)d_in[0];
    const float* Wq   = (const float*)d_in[1];
    const float* Wk   = (const float*)d_in[2];
    const float* Wv   = (const float*)d_in[3];
    const float* Wp   = (const float*)d_in[4];
    const float* bias = (const float*)d_in[5];
    float* out = (float*)d_out;

    cudaFuncSetAttribute(attn_kernel, cudaFuncAttributeMaxDynamicSharedMemorySize, ATTN_SMEM);
    cudaFuncSetAttribute(gemm_kernel<0>, cudaFuncAttributeMaxDynamicSharedMemorySize, GEMM_SMEM);
    cudaFuncSetAttribute(gemm_kernel<1>, cudaFuncAttributeMaxDynamicSharedMemorySize, GEMM_SMEM);

    // 1) fp16 conversions (single kernel)
    conv_all_kernel<<<CONV_BLOCKS, 256>>>(x, Wp, Wq, Wk, Wv);

    // 2) QKV projection (pure fp16 1-pass HMMA; Q/K outputs split hi/lo)
    gemm_kernel<0><<<dim3(64, 12), 256, GEMM_SMEM>>>(nullptr, nullptr);

    // 3) causal attention (QK 3-pass, PV 1-pass)
    attn_kernel<<<dim3(8, 16, 8), 256, ATTN_SMEM>>>();

    // 4) output projection (1-pass) + bias
    gemm_kernel<1><<<dim3(64, 4), 256, GEMM_SMEM>>>(bias, out);
}

// round 17
// speedup vs baseline: 1.5017x; 1.5017x over previous
#include <cuda_runtime.h>
#include <cuda_fp16.h>
#include <math.h>
#include <cstdint>

#define B_  8
#define T_  1024
#define C_  1024
#define H_  16
#define D_  64
#define M_  (B_*T_)    // 8192
#define HD_ (H_*D_)    // 1024
#define NQKV_ (3*HD_)  // 3072

// ---------------- scratch (static device globals) ----------------
__device__ unsigned short g_xhi[M_*C_],  g_xlo[M_*C_];       // x split [M][K]
__device__ unsigned short g_bhi[NQKV_*C_], g_blo[NQKV_*C_];  // qkv W as B[n][k]
__device__ unsigned short g_phi[C_*HD_];                     // proj W hi as B[n][k]
__device__ unsigned short g_atthi[M_*HD_];                   // attn out (fp16) [M][HD]
__device__ unsigned short g_qhi[B_*H_*T_*D_], g_qlo[B_*H_*T_*D_];  // [b,h,t,d]
__device__ unsigned short g_khi[B_*H_*T_*D_], g_klo[B_*H_*T_*D_];  // [b,h,t,d]
__device__ unsigned short g_vhi[B_*H_*T_*D_];                // TRANSPOSED: [b,h,d,t], hi only

// ---------------- helpers ----------------
__device__ __forceinline__ uint32_t smem_u32(const void* p) {
    uint32_t a;
    asm("{ .reg .u64 t; cvta.to.shared.u64 t, %1; cvt.u32.u64 %0, t; }" : "=r"(a) : "l"(p));
    return a;
}
__device__ __forceinline__ void cp16(uint32_t dst, const void* src) {
    asm volatile("cp.async.cg.shared.global [%0], [%1], 16;" :: "r"(dst), "l"(src));
}
#define CP_COMMIT() asm volatile("cp.async.commit_group;" ::: "memory")
#define CP_WAIT0()  asm volatile("cp.async.wait_group 0;" ::: "memory")

__device__ __forceinline__ void ldsm_x4(uint32_t* r, uint32_t addr) {
    asm volatile("ldmatrix.sync.aligned.m8n8.x4.shared.b16 {%0,%1,%2,%3}, [%4];"
        : "=r"(r[0]), "=r"(r[1]), "=r"(r[2]), "=r"(r[3]) : "r"(addr));
}
__device__ __forceinline__ void mma16816(float* d, const uint32_t* a, const uint32_t* b) {
    asm volatile("mma.sync.aligned.m16n8k16.row.col.f32.f16.f16.f32 "
        "{%0,%1,%2,%3}, {%4,%5,%6,%7}, {%8,%9}, {%0,%1,%2,%3};"
        : "+f"(d[0]), "+f"(d[1]), "+f"(d[2]), "+f"(d[3])
        : "r"(a[0]), "r"(a[1]), "r"(a[2]), "r"(a[3]), "r"(b[0]), "r"(b[1]));
}
__device__ __forceinline__ void split_h(float v, __half& hi, __half& lo) {
    hi = __float2half_rn(v);
    lo = __float2half_rn(v - __half2float(hi));
}
__device__ __forceinline__ uint32_t packh2(float a, float b) {
    __half2 t = __floats2half2_rn(a, b);
    return *(uint32_t*)&t;
}
// fast exp2 on FMA pipe, degree-5 (x <= 0 expected; clamped)
__device__ __forceinline__ float exp2fast(float x) {
    x = fmaxf(x, -120.0f);
    float t = x + 12582912.0f;
    int   n = __float_as_int(t) - 0x4B400000;
    float f = x - (t - 12582912.0f);
    float p = fmaf(f, 0.0015403f, 0.0096181f);
    p = fmaf(f, p, 0.0555041f);
    p = fmaf(f, p, 0.2402265f);
    p = fmaf(f, p, 0.6931472f);
    p = fmaf(f, p, 1.0f);
    return __int_as_float(__float_as_int(p) + (n << 23));
}

// ---------------------------------------------------------------------------
// Single merged conversion kernel (identical to round 15).
// ---------------------------------------------------------------------------
#define NXB   (M_*C_/4/256)         // 8192
#define NWPB  1024
#define CONV_BLOCKS (NXB + NWPB + 3*512)

__global__ __launch_bounds__(256) void conv_all_kernel(
    const float* __restrict__ x,  const float* __restrict__ Wp,
    const float* __restrict__ Wq, const float* __restrict__ Wk,
    const float* __restrict__ Wv)
{
    const int bi = blockIdx.x;
    if (bi < NXB) {
        int i = bi * 256 + threadIdx.x;
        float4 v = ((const float4*)x)[i];
        __half h[4], l[4];
        split_h(v.x, h[0], l[0]); split_h(v.y, h[1], l[1]);
        split_h(v.z, h[2], l[2]); split_h(v.w, h[3], l[3]);
        __half2* ph = (__half2*)g_xhi;
        __half2* pl = (__half2*)g_xlo;
        ph[i*2]   = __halves2half2(h[0], h[1]);
        ph[i*2+1] = __halves2half2(h[2], h[3]);
        pl[i*2]   = __halves2half2(l[0], l[1]);
        pl[i*2+1] = __halves2half2(l[2], l[3]);
    } else if (bi < NXB + NWPB) {
        __shared__ float tile[32][33];
        const int idx = bi - NXB;
        const int bx = idx >> 5, by = idx & 31;
        const int tx = threadIdx.x & 31, ty = threadIdx.x >> 5;
#pragma unroll
        for (int r = 0; r < 4; r++)
            tile[ty + 8*r][tx] = Wp[(size_t)(by*32 + ty + 8*r) * C_ + bx*32 + tx];
        __syncthreads();
#pragma unroll
        for (int r = 0; r < 4; r++) {
            float v = tile[tx][ty + 8*r];
            size_t id = (size_t)(bx*32 + ty + 8*r) * C_ + by*32 + tx;
            ((__half*)g_phi)[id] = __float2half_rn(v);
        }
    } else {
        __shared__ float tile[32][65];
        const int idx = bi - NXB - NWPB;          // 0..1535
        const int sel = idx >> 9;                 // 0=q,1=k,2=v
        const int id2 = idx & 511;
        const int h = id2 & 15, kt = id2 >> 4;
        const int n0 = sel << 10;
        const float* W = (sel == 0) ? Wq : ((sel == 1) ? Wk : Wv);
        const int tid = threadIdx.x;
        const float* src = W + (size_t)h * (C_ * D_) + (size_t)kt * 32 * D_;
#pragma unroll
        for (int i = 0; i < 8; i++) {
            int u = i * 256 + tid;
            tile[u >> 6][u & 63] = src[(size_t)(u >> 6) * D_ + (u & 63)];
        }
        __syncthreads();
        const int d = tid >> 2, seg = tid & 3;
        __half2* dh = (__half2*)(g_bhi + (size_t)(n0 + h*64 + d) * C_ + kt*32 + seg*8);
        __half2* dl = (__half2*)(g_blo + (size_t)(n0 + h*64 + d) * C_ + kt*32 + seg*8);
#pragma unroll
        for (int j = 0; j < 4; j++) {
            __half h0, l0, h1, l1;
            split_h(tile[seg*8 + j*2][d],     h0, l0);
            split_h(tile[seg*8 + j*2 + 1][d], h1, l1);
            dh[j] = __halves2half2(h0, h1);
            if (sel != 2) dl[j] = __halves2half2(l0, l1);
        }
    }
}

// ---------------------------------------------------------------------------
// mma.sync fp16 GEMM. ROUND-15 LAYOUT (stage 92160 B, BLO slot retained).
// ONLY change vs round 15: p2 = false (QKV is 1-pass everywhere).
// ---------------------------------------------------------------------------
#define ROWB        144
#define A_BYTES     (128*ROWB)      // 18432
#define B_BYTES     (256*ROWB)      // 36864
#define OFF_AHI     0
#define OFF_BHI     A_BYTES
#define OFF_BLO     (A_BYTES + B_BYTES)
#define STAGE_BYTES (A_BYTES + 2*B_BYTES)     // 92160  (round-15 geometry)
#define GEMM_SMEM   (2*STAGE_BYTES)           // 184320
#define NCHUNK      16

template<int MODE>
__global__ __launch_bounds__(256, 1) void gemm_kernel(const float* __restrict__ bias,
                                                      float* __restrict__ out) {
    extern __shared__ char smem[];
    const int tid  = threadIdx.x;
    const int wid  = tid >> 5;
    const int lane = tid & 31;
    const int m0 = blockIdx.x * 128;
    const int n0 = blockIdx.y * 256;

    // ROUND-17 CHANGE: pass-2 disabled everywhere (1-pass QKV & proj)
    const bool p2 = false;

    const __half* Ahi = (MODE == 0) ? (const __half*)g_xhi : (const __half*)g_atthi;
    const __half* Bhi = (MODE == 0) ? (const __half*)g_bhi : (const __half*)g_phi;
    const __half* Blo = (const __half*)g_blo;

    const uint32_t sb0 = smem_u32(smem);

    auto load_stage = [&](int c, int s) {
        const uint32_t base = sb0 + s * STAGE_BYTES;
        const int k0 = c * 64;
#pragma unroll
        for (int i = 0; i < 4; i++) {
            int u = i * 256 + tid;
            int r = u >> 3, kc = (u & 7) * 8;
            uint32_t doff = r * ROWB + (u & 7) * 16;
            cp16(base + OFF_AHI + doff, Ahi + (size_t)(m0 + r) * C_ + k0 + kc);
        }
#pragma unroll
        for (int i = 0; i < 8; i++) {
            int u = i * 256 + tid;
            int r = u >> 3, kc = (u & 7) * 8;
            uint32_t doff = r * ROWB + (u & 7) * 16;
            cp16(base + OFF_BHI + doff, Bhi + (size_t)(n0 + r) * C_ + k0 + kc);
            if (p2)
                cp16(base + OFF_BLO + doff, Blo + (size_t)(n0 + r) * C_ + k0 + kc);
        }
    };

    const int warp_m = wid & 1;      // 2 x 64 rows
    const int warp_n = wid >> 1;     // 4 x 64 cols
    const int mati = lane >> 3;
    const int ri   = lane & 7;

    float acc[4][8][4];
#pragma unroll
    for (int a = 0; a < 4; a++)
#pragma unroll
        for (int b = 0; b < 8; b++)
#pragma unroll
            for (int c = 0; c < 4; c++) acc[a][b][c] = 0.0f;

    load_stage(0, 0); CP_COMMIT();

    for (int c = 0; c < NCHUNK; c++) {
        CP_WAIT0();
        __syncthreads();
        if (c + 1 < NCHUNK) { load_stage(c + 1, (c + 1) & 1); CP_COMMIT(); }

        const uint32_t base = sb0 + (c & 1) * STAGE_BYTES;
#pragma unroll
        for (int kc = 0; kc < 64; kc += 16) {
            uint32_t ah[4][4];
#pragma unroll
            for (int mt = 0; mt < 4; mt++) {
                int row = warp_m*64 + mt*16 + ri + (mati & 1) * 8;
                int kk  = kc + (mati >> 1) * 8;
                ldsm_x4(ah[mt], base + OFF_AHI + row * ROWB + kk * 2);
            }
            uint32_t bh[4][4], bl[4][4];
#pragma unroll
            for (int nt4 = 0; nt4 < 4; nt4++) {
                int n  = warp_n*64 + nt4*16 + ri + (mati >> 1) * 8;
                int kk = kc + (mati & 1) * 8;
                ldsm_x4(bh[nt4], base + OFF_BHI + n * ROWB + kk * 2);
                if (p2) ldsm_x4(bl[nt4], base + OFF_BLO + n * ROWB + kk * 2);
            }
            // PASS-MAJOR over 32 independent accumulators
#pragma unroll
            for (int mt = 0; mt < 4; mt++)
#pragma unroll
                for (int nt = 0; nt < 8; nt++)
                    mma16816(acc[mt][nt], ah[mt], &bh[nt >> 1][(nt & 1) * 2]);
            if (p2) {
#pragma unroll
                for (int mt = 0; mt < 4; mt++)
#pragma unroll
                    for (int nt = 0; nt < 8; nt++)
                        mma16816(acc[mt][nt], ah[mt], &bl[nt >> 1][(nt & 1) * 2]);
            }
        }
        __syncthreads();
    }

    const int r4 = lane >> 2;
    const int c2 = (lane & 3) * 2;
#pragma unroll
    for (int mt = 0; mt < 4; mt++) {
#pragma unroll
        for (int nt = 0; nt < 8; nt++) {
            const int n = n0 + warp_n*64 + nt*8 + c2;
#pragma unroll
            for (int half = 0; half < 2; half++) {
                const int row = m0 + warp_m*64 + mt*16 + r4 + half*8;
                float2 v = make_float2(acc[mt][nt][half*2], acc[mt][nt][half*2 + 1]);
                if (MODE == 0) {
                    const int type = n >> 10;
                    const int bb = row >> 10, tt = row & 1023;
                    const int h2 = (n & 1023) >> 6, d2 = n & 63;
                    if (type == 2) {
                        // V transposed hi only: [b,h,d,t]
                        const size_t idx = ((size_t)(bb*H_ + h2) * D_ + d2) * T_ + tt;
                        ((__half*)g_vhi)[idx]      = __float2half_rn(v.x);
                        ((__half*)g_vhi)[idx + T_] = __float2half_rn(v.y);
                    } else {
                        unsigned short* dh = (type == 0) ? g_qhi : g_khi;
                        unsigned short* dl = (type == 0) ? g_qlo : g_klo;
                        const size_t idx = (size_t)(((bb*H_ + h2)*T_ + tt)) * D_ + d2;
                        __half hx, lx, hy, ly;
                        split_h(v.x, hx, lx); split_h(v.y, hy, ly);
                        *(__half2*)(dh + idx) = __halves2half2(hx, hy);
                        *(__half2*)(dl + idx) = __halves2half2(lx, ly);
                    }
                } else {
                    float2 bv = *(const float2*)(bias + n);
                    v.x += bv.x; v.y += bv.y;
                    *(float2*)(out + (size_t)row * C_ + n) = v;
                }
            }
        }
    }
}

// ---------------------------------------------------------------------------
// Tensor-core causal flash attention (round-15 validated, byte-identical).
// QK 3-pass (corrects Q/K storage rounding), PV 1-pass. One sync per tile.
// ---------------------------------------------------------------------------
#define AROWB     144
#define VROWB     272
#define A_QHI     0
#define A_QLO     18432
#define A_STAGE0  36864
#define A_STAGEB  54272
#define A_KHI     0
#define A_KLO     18432
#define A_VHI     36864
#define ATTN_SMEM 145408
#define SCL       0.18033688f   // 0.125 * log2(e)

__global__ __launch_bounds__(256, 1) void attn_kernel() {
    extern __shared__ char smem[];
    const uint32_t sb = smem_u32(smem);
    const int tid = threadIdx.x, wid = tid >> 5, lane = tid & 31;
    const int qb = 7 - (int)blockIdx.x;                 // heavy blocks first
    const int h = blockIdx.y, b = blockIdx.z;
    const size_t hoff = (size_t)(b*H_ + h) * T_ * D_;

    const __half* Qh = (const __half*)g_qhi + hoff;
    const __half* Ql = (const __half*)g_qlo + hoff;
    const __half* Kh = (const __half*)g_khi + hoff;
    const __half* Kl = (const __half*)g_klo + hoff;
    const __half* Vh = (const __half*)g_vhi + hoff;    // [d][t]

    const int nkt = qb + 1;
    const int ri = lane & 7, mati = lane >> 3;

    auto load_kv = [&](int kt, int st) {
        const uint32_t base = sb + A_STAGE0 + st * A_STAGEB;
#pragma unroll
        for (int i = 0; i < 4; i++) {
            int u = i * 256 + tid;                  // 0..1023
            int r = u >> 3, cc = u & 7;
            const size_t off = (size_t)(kt*128 + r) * D_ + cc*8;
            uint32_t doff = r * AROWB + cc * 16;
            cp16(base + A_KHI + doff, Kh + off);
            cp16(base + A_KLO + doff, Kl + off);
        }
#pragma unroll
        for (int i = 0; i < 4; i++) {
            int u = i * 256 + tid;                  // 0..1023
            int r = u >> 4, cc = u & 15;
            const size_t off = (size_t)r * T_ + kt*128 + cc*8;
            uint32_t doff = r * VROWB + cc * 16;
            cp16(base + A_VHI + doff, Vh + off);
        }
    };

    // Q tile (128 x 64)
#pragma unroll
    for (int i = 0; i < 4; i++) {
        int u = i * 256 + tid;
        int r = u >> 3, cc = u & 7;
        const size_t off = (size_t)(qb*128 + r) * D_ + cc*8;
        uint32_t doff = r * AROWB + cc * 16;
        cp16(sb + A_QHI + doff, Qh + off);
        cp16(sb + A_QLO + doff, Ql + off);
    }
    load_kv(0, 0);
    CP_COMMIT();

    float o[8][4];
#pragma unroll
    for (int j = 0; j < 8; j++)
#pragma unroll
        for (int e = 0; e < 4; e++) o[j][e] = 0.0f;
    float mA = -1e30f, mB = -1e30f, lA = 0.0f, lB = 0.0f;
    uint32_t qhf[4][4], qlf[4][4];

    const int w0 = qb*128 + wid*16;
    const int rA = w0 + (lane >> 2);
    const int rB = rA + 8;

    for (int kt = 0; kt < nkt; kt++) {
        CP_WAIT0();
        __syncthreads();
        if (kt + 1 < nkt) { load_kv(kt + 1, (kt + 1) & 1); CP_COMMIT(); }

        const uint32_t kvb = sb + A_STAGE0 + (kt & 1) * A_STAGEB;

        if (kt == 0) {
#pragma unroll
            for (int t = 0; t < 4; t++) {
                int row = wid*16 + ri + (mati & 1) * 8;
                int kk  = t*16 + (mati >> 1) * 8;
                ldsm_x4(qhf[t], sb + A_QHI + row * AROWB + kk * 2);
                ldsm_x4(qlf[t], sb + A_QLO + row * AROWB + kk * 2);
            }
        }

        // ---- S = Q K^T over 128 keys (3-pass, pass-major) ----
        float s[16][4];
#pragma unroll
        for (int j = 0; j < 16; j++)
#pragma unroll
            for (int e = 0; e < 4; e++) s[j][e] = 0.0f;
#pragma unroll
        for (int half = 0; half < 2; half++) {
#pragma unroll
            for (int t = 0; t < 4; t++) {
                uint32_t kh[4][4], kl[4][4];
#pragma unroll
                for (int g = 0; g < 4; g++) {
                    int n  = half*64 + g*16 + ri + (mati >> 1) * 8;
                    int kk = t*16 + (mati & 1) * 8;
                    ldsm_x4(kh[g], kvb + A_KHI + n * AROWB + kk * 2);
                    ldsm_x4(kl[g], kvb + A_KLO + n * AROWB + kk * 2);
                }
#pragma unroll
                for (int nt = 0; nt < 8; nt++)
                    mma16816(s[half*8 + nt], qhf[t], &kh[nt >> 1][(nt & 1) * 2]);
#pragma unroll
                for (int nt = 0; nt < 8; nt++)
                    mma16816(s[half*8 + nt], qhf[t], &kl[nt >> 1][(nt & 1) * 2]);
#pragma unroll
                for (int nt = 0; nt < 8; nt++)
                    mma16816(s[half*8 + nt], qlf[t], &kh[nt >> 1][(nt & 1) * 2]);
            }
        }

        // ---- scale (log2 domain) + causal mask (only final tile masks) ----
        const bool need_mask = (kt == qb);
#pragma unroll
        for (int sg = 0; sg < 16; sg++) {
#pragma unroll
            for (int e = 0; e < 4; e++) {
                float v = s[sg][e] * SCL;
                if (need_mask) {
                    const int col = kt*128 + sg*8 + (lane & 3)*2 + (e & 1);
                    const int row = (e < 2) ? rA : rB;
                    if (col > row) v = -1e30f;
                }
                s[sg][e] = v;
            }
        }

        // ---- online softmax ----
        float mxA = -1e30f, mxB = -1e30f;
#pragma unroll
        for (int sg = 0; sg < 16; sg++) {
            mxA = fmaxf(mxA, fmaxf(s[sg][0], s[sg][1]));
            mxB = fmaxf(mxB, fmaxf(s[sg][2], s[sg][3]));
        }
#pragma unroll
        for (int off = 1; off <= 2; off <<= 1) {
            mxA = fmaxf(mxA, __shfl_xor_sync(0xffffffffu, mxA, off));
            mxB = fmaxf(mxB, __shfl_xor_sync(0xffffffffu, mxB, off));
        }
        const float mAn = fmaxf(mA, mxA), mBn = fmaxf(mB, mxB);
        const float fA = exp2fast(mA - mAn), fB = exp2fast(mB - mBn);
        float sumA = 0.0f, sumB = 0.0f;
#pragma unroll
        for (int sg = 0; sg < 16; sg++) {
            s[sg][0] = exp2fast(s[sg][0] - mAn);
            s[sg][1] = exp2fast(s[sg][1] - mAn);
            s[sg][2] = exp2fast(s[sg][2] - mBn);
            s[sg][3] = exp2fast(s[sg][3] - mBn);
            sumA += s[sg][0] + s[sg][1];
            sumB += s[sg][2] + s[sg][3];
        }
#pragma unroll
        for (int off = 1; off <= 2; off <<= 1) {
            sumA += __shfl_xor_sync(0xffffffffu, sumA, off);
            sumB += __shfl_xor_sync(0xffffffffu, sumB, off);
        }
        lA = lA * fA + sumA;
        lB = lB * fB + sumB;
        mA = mAn; mB = mBn;
#pragma unroll
        for (int nt = 0; nt < 8; nt++) {
            o[nt][0] *= fA; o[nt][1] *= fA;
            o[nt][2] *= fB; o[nt][3] *= fB;
        }

        // ---- P -> fp16 A fragments (registers only) ----
        uint32_t pa[8][4];
#pragma unroll
        for (int t = 0; t < 8; t++) {
            pa[t][0] = packh2(s[2*t][0],   s[2*t][1]);
            pa[t][1] = packh2(s[2*t][2],   s[2*t][3]);
            pa[t][2] = packh2(s[2*t+1][0], s[2*t+1][1]);
            pa[t][3] = packh2(s[2*t+1][2], s[2*t+1][3]);
        }

        // ---- O += P V (1-pass), V^T tile + plain ldmatrix ----
#pragma unroll
        for (int t = 0; t < 8; t++) {
            uint32_t vh[4][4];
#pragma unroll
            for (int g = 0; g < 4; g++) {
                int n  = g*16 + ri + (mati >> 1) * 8;       // d row of V^T
                int kk = t*16 + (mati & 1) * 8;             // key col
                ldsm_x4(vh[g], kvb + A_VHI + n * VROWB + kk * 2);
            }
#pragma unroll
            for (int nt = 0; nt < 8; nt++)
                mma16816(o[nt], pa[t], &vh[nt >> 1][(nt & 1) * 2]);
        }
        // no trailing sync: next iteration's top sync orders stage reuse
    }

    // ---- epilogue: normalize + fp16 att ----
    const float iA = 1.0f / lA, iB = 1.0f / lB;
#pragma unroll
    for (int nt = 0; nt < 8; nt++) {
        const int col = h*64 + nt*8 + (lane & 3)*2;
        {
            const size_t idx = (size_t)(b*T_ + rA) * HD_ + col;
            *(__half2*)((__half*)g_atthi + idx) =
                __floats2half2_rn(o[nt][0] * iA, o[nt][1] * iA);
        }
        {
            const size_t idx = (size_t)(b*T_ + rB) * HD_ + col;
            *(__half2*)((__half*)g_atthi + idx) =
                __floats2half2_rn(o[nt][2] * iB, o[nt][3] * iB);
        }
    }
}

// ---------------------------------------------------------------------------
extern "C" void kernel_launch(void* const* d_in, const int* in_sizes, int n_in,
                              void* d_out, int out_size)
{
    (void)in_sizes; (void)n_in; (void)out_size;
    const float* x    = (const float*)d_in[0];
    const float* Wq   = (const float*)d_in[1];
    const float* Wk   = (const float*)d_in[2];
    const float* Wv   = (const float*)d_in[3];
    const float* Wp   = (const float*)d_in[4];
    const float* bias = (const float*)d_in[5];
    float* out = (float*)d_out;

    cudaFuncSetAttribute(attn_kernel, cudaFuncAttributeMaxDynamicSharedMemorySize, ATTN_SMEM);
    cudaFuncSetAttribute(gemm_kernel<0>, cudaFuncAttributeMaxDynamicSharedMemorySize, GEMM_SMEM);
    cudaFuncSetAttribute(gemm_kernel<1>, cudaFuncAttributeMaxDynamicSharedMemorySize, GEMM_SMEM);

    // 1) precision-split conversions (round-15 kernel, unchanged)
    conv_all_kernel<<<CONV_BLOCKS, 256>>>(x, Wp, Wq, Wk, Wv);

    // 2) QKV projection (1-pass HMMA, round-15 smem geometry)
    gemm_kernel<0><<<dim3(64, 12), 256, GEMM_SMEM>>>(nullptr, nullptr);

    // 3) causal attention (QK 3-pass, PV 1-pass)
    attn_kernel<<<dim3(8, 16, 8), 256, ATTN_SMEM>>>();

    // 4) output projection (1-pass) + bias
    gemm_kernel<1><<<dim3(64, 4), 256, GEMM_SMEM>>>(bias, out);
}